// round 15
// baseline (speedup 1.0000x reference)
#include <cuda_runtime.h>
#include <cstdint>

#define BS   4
#define SEQ  128
#define DIM  768
#define HID  768
#define NOUT 2
#define MROWS (BS * SEQ)                    // 512

// ---------------- device scratch (no allocation allowed) -------------------
__device__ float g_ha[MROWS * HID];         // a @ W1[:D]        (final)
__device__ float g_hb[MROWS * HID];         // b @ W1[D:] + b1   (final)

// ---------------------------------------------------------------------------
__device__ __forceinline__ uint32_t smem_u32(const void* p) {
    uint32_t a;
    asm("{ .reg .u64 t; cvta.to.shared.u64 t, %1; cvt.u32.u64 %0, t; }"
        : "=r"(a) : "l"(p));
    return a;
}

__device__ __forceinline__ void cp_async16(uint32_t saddr, const void* gptr) {
    asm volatile("cp.async.cg.shared.global [%0], [%1], 16;"
                 :: "r"(saddr), "l"(gptr) : "memory");
}
__device__ __forceinline__ void cp_commit() {
    asm volatile("cp.async.commit_group;" ::: "memory");
}
template <int N>
__device__ __forceinline__ void cp_wait() {
    asm volatile("cp.async.wait_group %0;" :: "n"(N) : "memory");
}

__device__ __forceinline__ uint32_t f2tf32(float x) {
    uint32_t u;
    asm("cvt.rna.tf32.f32 %0, %1;" : "=r"(u) : "f"(x));
    return u;
}

__device__ __forceinline__ void ldsm_x4(uint32_t* d, uint32_t saddr) {
    asm volatile(
        "ldmatrix.sync.aligned.m8n8.x4.shared.b16 {%0,%1,%2,%3}, [%4];"
        : "=r"(d[0]), "=r"(d[1]), "=r"(d[2]), "=r"(d[3]) : "r"(saddr));
}

__device__ __forceinline__ void mma_tf32(float* c, const uint32_t* a,
                                         const uint32_t* b) {
    asm volatile(
        "mma.sync.aligned.m16n8k8.row.col.f32.tf32.tf32.f32 "
        "{%0,%1,%2,%3}, {%4,%5,%6,%7}, {%8,%9}, {%0,%1,%2,%3};"
        : "+f"(c[0]), "+f"(c[1]), "+f"(c[2]), "+f"(c[3])
        : "r"(a[0]), "r"(a[1]), "r"(a[2]), "r"(a[3]), "r"(b[0]), "r"(b[1]));
}

// ---------------------------------------------------------------------------
// Kernel 1: projection GEMM — SPLIT-N version (no merge needed).
// z=0: g_ha = a @ W1[0:768]; z=1: g_hb = b @ W1[768:1536] + b1.
// CTA tile 64m x 32n, full K=768 (24 chunks of BK=32). 128 threads =
// 4 warps (2m x 2n), warp tile 32m x 16n. ldmatrix A frags, in-reg cvt.rna,
// 3-stage cp.async pipeline. Grid (24, 8, 2) = 384 CTAs. Dyn smem 43008 B.
// ---------------------------------------------------------------------------
#define ALD 36
#define BLD 40
#define STG_A (64 * ALD)                     // 2304 floats
#define STG_B (32 * BLD)                     // 1280 floats
#define PROJ_SMEM_BYTES (3 * (STG_A + STG_B) * 4)   // 43008

__global__ __launch_bounds__(128) void proj_tc(
    const float* __restrict__ a, const float* __restrict__ b,
    const float* __restrict__ W1, const float* __restrict__ b1)
{
    extern __shared__ float psm[];
    float* const Asm = psm;
    float* const Bsm = psm + 3 * STG_A;

    const int tid = threadIdx.x;
    const int wid = tid >> 5;
    const int lane = tid & 31;
    const int r = lane >> 2;                 // 0..7
    const int c = lane & 3;                  // 0..3
    const int wm = (wid >> 1) * 32;          // {0,32}
    const int wn = (wid & 1) * 16;           // {0,16}

    const int n0 = blockIdx.x * 32;
    const int m0 = blockIdx.y * 64;
    const int z  = blockIdx.z;

    const float* __restrict__ X = z ? b : a;
    const float* __restrict__ W = W1 + (size_t)z * DIM * HID;

    const uint32_t sA = smem_u32(Asm);
    const uint32_t sB = smem_u32(Bsm);

    const uint32_t a_lm0 =
        (uint32_t)(((wm + (lane & 7) + ((lane >> 3) & 1) * 8) * ALD
                    + ((lane >> 4) & 1) * 4) * 4);

    // per-chunk loads: A 64x32 = 512 f4 (4/thread), B 32x32 = 256 f4 (2/thread)
    auto ldchunk = [&](int chunk, int s) {
        const int k0 = chunk * 32;
        #pragma unroll
        for (int i = 0; i < 4; i++) {
            int f = i * 128 + tid;
            int row = f >> 3, kc = (f & 7) * 4;
            cp_async16(sA + (uint32_t)(s * STG_A + row * ALD + kc) * 4,
                       X + (size_t)(m0 + row) * DIM + k0 + kc);
        }
        #pragma unroll
        for (int i = 0; i < 2; i++) {
            int f = i * 128 + tid;
            int kr = f >> 3, nc = (f & 7) * 4;
            cp_async16(sB + (uint32_t)(s * STG_B + kr * BLD + nc) * 4,
                       W + (size_t)(k0 + kr) * HID + n0 + nc);
        }
        cp_commit();
    };

    float acc[2][2][4] = {};

    ldchunk(0, 0);
    ldchunk(1, 1);

    for (int chunk = 0; chunk < 24; chunk++) {
        const int s = chunk % 3;
        if (chunk < 23) cp_wait<1>(); else cp_wait<0>();
        __syncthreads();

        if (chunk + 2 < 24) ldchunk(chunk + 2, (chunk + 2) % 3);

        const uint32_t aStage = sA + (uint32_t)(s * STG_A) * 4;
        const float* Bb = Bsm + s * STG_B;
        #pragma unroll
        for (int ks = 0; ks < 4; ks++) {
            const int kb = ks * 8;
            uint32_t af[2][4];
            #pragma unroll
            for (int mt = 0; mt < 2; mt++) {
                ldsm_x4(af[mt], aStage + a_lm0
                                + (uint32_t)(mt * 16 * ALD + kb) * 4);
                af[mt][0] = f2tf32(__uint_as_float(af[mt][0]));
                af[mt][1] = f2tf32(__uint_as_float(af[mt][1]));
                af[mt][2] = f2tf32(__uint_as_float(af[mt][2]));
                af[mt][3] = f2tf32(__uint_as_float(af[mt][3]));
            }
            uint32_t bf[2][2];
            #pragma unroll
            for (int nt = 0; nt < 2; nt++) {
                const float* bp = Bb + (kb + c) * BLD + wn + nt * 8 + r;
                bf[nt][0] = f2tf32(bp[0]);
                bf[nt][1] = f2tf32(bp[4 * BLD]);
            }
            #pragma unroll
            for (int nt = 0; nt < 2; nt++)
                #pragma unroll
                for (int mt = 0; mt < 2; mt++)
                    mma_tf32(acc[mt][nt], af[mt], bf[nt]);
        }
    }

    // epilogue: single final write (+ b1 for z=1)
    float* __restrict__ outp = z ? g_hb : g_ha;
    #pragma unroll
    for (int mt = 0; mt < 2; mt++) {
        #pragma unroll
        for (int nt = 0; nt < 2; nt++) {
            int m = m0 + wm + mt * 16 + r;
            int n = n0 + wn + nt * 8 + c * 2;
            float2 v0 = make_float2(acc[mt][nt][0], acc[mt][nt][1]);
            float2 v1 = make_float2(acc[mt][nt][2], acc[mt][nt][3]);
            if (z) {
                float2 bb = *(const float2*)&b1[n];
                v0.x += bb.x; v0.y += bb.y;
                v1.x += bb.x; v1.y += bb.y;
            }
            *(float2*)&outp[(size_t)m * HID + n] = v0;
            *(float2*)&outp[(size_t)(m + 8) * HID + n] = v1;
        }
    }
}

// ---------------------------------------------------------------------------
// Kernel 2: pairwise relu + reduce to O=2 — R13 geometry (measured 15.7us),
// single-buffer reads. Tile 16s x 16t, grid (8, 8, 4) = 256 CTAs,
// 256 threads (low regs, 4 CTA/SM ceiling). 4 h-groups of 64 threads
// (192 h each, 6 chunks of 32 h). Thread tile 2s x 2t. 2-step smem tree.
// ---------------------------------------------------------------------------
#define QLD 36
#define QA_G (16 * QLD)                      // 576 floats per group
#define QB_BASE (4 * QA_G)                   // 2304
#define QW_BASE (QB_BASE + 4 * QA_G)         // 4608
#define QW_G 72

__global__ __launch_bounds__(256, 4) void pair_kernel(
    const float* __restrict__ W2, const float* __restrict__ b2,
    float* __restrict__ out)
{
    __shared__ float sm[QW_BASE + 4 * QW_G];     // 19584 B

    const int tt = blockIdx.x;              // t tile (16)
    const int st = blockIdx.y;              // s tile (16)
    const int batch = blockIdx.z;

    const int tid = threadIdx.x;
    const int g  = tid >> 6;                // 0..3 h-group
    const int lt = tid & 63;
    const int sq = lt >> 3;                 // 0..7
    const int tq = lt & 7;                  // 0..7

    float* const sA = sm + g * QA_G;                 // [16][QLD]
    float* const sB = sm + QB_BASE + g * QA_G;       // [16][QLD]
    float* const sW = sm + QW_BASE + g * QW_G;       // [64]

    const float* __restrict__ hap =
        g_ha + (size_t)(batch * SEQ + st * 16) * HID;
    const float* __restrict__ hbp =
        g_hb + (size_t)(batch * SEQ + tt * 16) * HID;

    float acc[2][2][2] = {};                // [i(s)][j(t)][o]

    #pragma unroll 1
    for (int c = 0; c < 6; c++) {
        const int h0 = g * 192 + c * 32;

        // fills: 16 rows x 32 h = 128 f4 each; 2 f4 per thread (coalesced)
        #pragma unroll
        for (int q = 0; q < 2; q++) {
            int f = q * 64 + lt;
            int row = f >> 3, col = (f & 7) * 4;
            *(float4*)&sA[row * QLD + col] =
                *(const float4*)&hap[(size_t)row * HID + h0 + col];
            *(float4*)&sB[row * QLD + col] =
                *(const float4*)&hbp[(size_t)row * HID + h0 + col];
        }
        if (lt < 16)
            *(float4*)&sW[lt * 4] = *(const float4*)&W2[h0 * 2 + lt * 4];
        __syncthreads();

        #pragma unroll
        for (int hh = 0; hh < 32; hh += 4) {
            float4 A[2], B[2];
            A[0] = *(const float4*)&sA[sq * QLD + hh];
            A[1] = *(const float4*)&sA[(sq + 8) * QLD + hh];
            B[0] = *(const float4*)&sB[tq * QLD + hh];
            B[1] = *(const float4*)&sB[(tq + 8) * QLD + hh];
            float4 W0 = *(const float4*)&sW[2 * hh];
            float4 W1 = *(const float4*)&sW[2 * hh + 4];

            #pragma unroll
            for (int i = 0; i < 2; i++) {
                #pragma unroll
                for (int j = 0; j < 2; j++) {
                    float r;
                    r = fmaxf(A[i].x + B[j].x, 0.f);
                    acc[i][j][0] += r * W0.x; acc[i][j][1] += r * W0.y;
                    r = fmaxf(A[i].y + B[j].y, 0.f);
                    acc[i][j][0] += r * W0.z; acc[i][j][1] += r * W0.w;
                    r = fmaxf(A[i].z + B[j].z, 0.f);
                    acc[i][j][0] += r * W1.x; acc[i][j][1] += r * W1.y;
                    r = fmaxf(A[i].w + B[j].w, 0.f);
                    acc[i][j][0] += r * W1.z; acc[i][j][1] += r * W1.w;
                }
            }
        }
        __syncthreads();
    }

    // ---- 2-step tree reduction across the 4 h-groups (alias over sm) ----
    float (*red)[64][12] = reinterpret_cast<float (*)[64][12]>(sm);
    float* af = (float*)acc;                // 8 floats
    // 4 -> 2
    if (g >= 2) {
        *(float4*)&red[g - 2][lt][0] = *(const float4*)&af[0];
        *(float4*)&red[g - 2][lt][4] = *(const float4*)&af[4];
    }
    __syncthreads();
    if (g < 2) {
        #pragma unroll
        for (int k = 0; k < 8; k++) af[k] += red[g][lt][k];
    }
    __syncthreads();
    // 2 -> 1
    if (g == 1) {
        *(float4*)&red[0][lt][0] = *(const float4*)&af[0];
        *(float4*)&red[0][lt][4] = *(const float4*)&af[4];
    }
    __syncthreads();
    if (g == 0) {
        const float c0 = b2[0], c1 = b2[1];
        #pragma unroll
        for (int i = 0; i < 2; i++) {
            #pragma unroll
            for (int j = 0; j < 2; j++) {
                int k0i = (i * 2 + j) * 2;
                float v0 = acc[i][j][0] + red[0][lt][k0i]     + c0;
                float v1 = acc[i][j][1] + red[0][lt][k0i + 1] + c1;
                int s = st * 16 + sq + 8 * i;
                int t = tt * 16 + tq + 8 * j;
                *(float2*)&out[(((size_t)batch * SEQ + s) * SEQ + t) * NOUT]
                    = make_float2(v0, v1);
            }
        }
    }
}

// ---------------------------------------------------------------------------
extern "C" void kernel_launch(void* const* d_in, const int* in_sizes, int n_in,
                              void* d_out, int out_size)
{
    const float* a  = (const float*)d_in[0];
    const float* b  = (const float*)d_in[1];
    const float* W1 = (const float*)d_in[2];
    const float* b1 = (const float*)d_in[3];
    const float* W2 = (const float*)d_in[4];
    const float* b2 = (const float*)d_in[5];
    float* out = (float*)d_out;

    cudaFuncSetAttribute(proj_tc, cudaFuncAttributeMaxDynamicSharedMemorySize,
                         PROJ_SMEM_BYTES);

    proj_tc<<<dim3(HID / 32, MROWS / 64, 2), 128, PROJ_SMEM_BYTES>>>(a, b, W1, b1);
    pair_kernel<<<dim3(SEQ / 16, SEQ / 16, BS), 256>>>(W2, b2, out);
}

// round 16
// speedup vs baseline: 1.1221x; 1.1221x over previous
#include <cuda_runtime.h>
#include <cstdint>

#define BS   4
#define SEQ  128
#define DIM  768
#define HID  768
#define NOUT 2
#define MROWS (BS * SEQ)                    // 512
#define KSPLIT 384                          // K per split-K half

// ---------------- device scratch (no allocation allowed) -------------------
__device__ float g_ha[MROWS * HID];         // partial: a @ W1[:D], k-half 0
__device__ float g_hb[MROWS * HID];         // partial: b @ W1[D:] + b1, k-half 0
__device__ float g_ha2[MROWS * HID];        // partial k-half 1
__device__ float g_hb2[MROWS * HID];        // partial k-half 1

// ---------------------------------------------------------------------------
__device__ __forceinline__ uint32_t smem_u32(const void* p) {
    uint32_t a;
    asm("{ .reg .u64 t; cvta.to.shared.u64 t, %1; cvt.u32.u64 %0, t; }"
        : "=r"(a) : "l"(p));
    return a;
}

__device__ __forceinline__ void cp_async16(uint32_t saddr, const void* gptr) {
    asm volatile("cp.async.cg.shared.global [%0], [%1], 16;"
                 :: "r"(saddr), "l"(gptr) : "memory");
}
__device__ __forceinline__ void cp_commit() {
    asm volatile("cp.async.commit_group;" ::: "memory");
}
template <int N>
__device__ __forceinline__ void cp_wait() {
    asm volatile("cp.async.wait_group %0;" :: "n"(N) : "memory");
}

__device__ __forceinline__ uint32_t f2tf32(float x) {
    uint32_t u;
    asm("cvt.rna.tf32.f32 %0, %1;" : "=r"(u) : "f"(x));
    return u;
}

__device__ __forceinline__ void ldsm_x4(uint32_t* d, uint32_t saddr) {
    asm volatile(
        "ldmatrix.sync.aligned.m8n8.x4.shared.b16 {%0,%1,%2,%3}, [%4];"
        : "=r"(d[0]), "=r"(d[1]), "=r"(d[2]), "=r"(d[3]) : "r"(saddr));
}

__device__ __forceinline__ void mma_tf32(float* c, const uint32_t* a,
                                         const uint32_t* b) {
    asm volatile(
        "mma.sync.aligned.m16n8k8.row.col.f32.tf32.tf32.f32 "
        "{%0,%1,%2,%3}, {%4,%5,%6,%7}, {%8,%9}, {%0,%1,%2,%3};"
        : "+f"(c[0]), "+f"(c[1]), "+f"(c[2]), "+f"(c[3])
        : "r"(a[0]), "r"(a[1]), "r"(a[2]), "r"(a[3]), "r"(b[0]), "r"(b[1]));
}

// ---------------------------------------------------------------------------
// Kernel 1: projection GEMM (R12 — best measured proj config, unchanged).
// mma.sync tf32, split-K=2 into separate partial buffers, BK=32,
// ldmatrix A frags, in-reg cvt.rna, 3-stage cp.async, CTA 64x64, 128 thr,
// warp tile 32x32. Grid (12, 8, 4) = 384 CTAs. Dyn smem 55296 B.
// ---------------------------------------------------------------------------
#define ALD 36
#define BLD 72
#define STG_A (64 * ALD)
#define STG_B (32 * BLD)
#define PROJ_SMEM_BYTES (3 * (STG_A + STG_B) * 4)   // 55296

__global__ __launch_bounds__(128) void proj_tc(
    const float* __restrict__ a, const float* __restrict__ b,
    const float* __restrict__ W1, const float* __restrict__ b1)
{
    extern __shared__ float psm[];
    float* const Asm = psm;
    float* const Bsm = psm + 3 * STG_A;

    const int tid = threadIdx.x;
    const int wid = tid >> 5;
    const int lane = tid & 31;
    const int r = lane >> 2;
    const int c = lane & 3;
    const int wm = (wid >> 1) * 32;
    const int wn = (wid & 1) * 32;

    const int n0 = blockIdx.x * 64;
    const int m0 = blockIdx.y * 64;
    const int z  = blockIdx.z & 1;
    const int kh = blockIdx.z >> 1;
    const int kbase = kh * KSPLIT;

    const float* __restrict__ X = z ? b : a;
    const float* __restrict__ W = W1 + (size_t)z * DIM * HID;

    const uint32_t sA = smem_u32(Asm);
    const uint32_t sB = smem_u32(Bsm);

    const uint32_t a_lm0 =
        (uint32_t)(((wm + (lane & 7) + ((lane >> 3) & 1) * 8) * ALD
                    + ((lane >> 4) & 1) * 4) * 4);

    auto ldchunk = [&](int chunk, int s) {
        const int k0 = kbase + chunk * 32;
        #pragma unroll
        for (int i = 0; i < 4; i++) {
            int f = i * 128 + tid;
            int row = f >> 3, kc = (f & 7) * 4;
            cp_async16(sA + (uint32_t)(s * STG_A + row * ALD + kc) * 4,
                       X + (size_t)(m0 + row) * DIM + k0 + kc);
        }
        #pragma unroll
        for (int i = 0; i < 4; i++) {
            int f = i * 128 + tid;
            int kr = f >> 4, nc = (f & 15) * 4;
            cp_async16(sB + (uint32_t)(s * STG_B + kr * BLD + nc) * 4,
                       W + (size_t)(k0 + kr) * HID + n0 + nc);
        }
        cp_commit();
    };

    float acc[2][4][4] = {};

    ldchunk(0, 0);
    ldchunk(1, 1);

    for (int chunk = 0; chunk < 12; chunk++) {
        const int s = chunk % 3;
        if (chunk < 11) cp_wait<1>(); else cp_wait<0>();
        __syncthreads();

        if (chunk + 2 < 12) ldchunk(chunk + 2, (chunk + 2) % 3);

        const uint32_t aStage = sA + (uint32_t)(s * STG_A) * 4;
        const float* Bb = Bsm + s * STG_B;
        #pragma unroll
        for (int ks = 0; ks < 4; ks++) {
            const int kb = ks * 8;
            uint32_t af[2][4];
            #pragma unroll
            for (int mt = 0; mt < 2; mt++) {
                ldsm_x4(af[mt], aStage + a_lm0
                                + (uint32_t)(mt * 16 * ALD + kb) * 4);
                af[mt][0] = f2tf32(__uint_as_float(af[mt][0]));
                af[mt][1] = f2tf32(__uint_as_float(af[mt][1]));
                af[mt][2] = f2tf32(__uint_as_float(af[mt][2]));
                af[mt][3] = f2tf32(__uint_as_float(af[mt][3]));
            }
            uint32_t bf[4][2];
            #pragma unroll
            for (int nt = 0; nt < 4; nt++) {
                const float* bp = Bb + (kb + c) * BLD + wn + nt * 8 + r;
                bf[nt][0] = f2tf32(bp[0]);
                bf[nt][1] = f2tf32(bp[4 * BLD]);
            }
            #pragma unroll
            for (int nt = 0; nt < 4; nt++)
                #pragma unroll
                for (int mt = 0; mt < 2; mt++)
                    mma_tf32(acc[mt][nt], af[mt], bf[nt]);
        }
    }

    float* __restrict__ outp = z ? (kh ? g_hb2 : g_hb) : (kh ? g_ha2 : g_ha);
    const bool addb = (z == 1) && (kh == 0);
    #pragma unroll
    for (int mt = 0; mt < 2; mt++) {
        #pragma unroll
        for (int nt = 0; nt < 4; nt++) {
            int m = m0 + wm + mt * 16 + r;
            int n = n0 + wn + nt * 8 + c * 2;
            float2 v0 = make_float2(acc[mt][nt][0], acc[mt][nt][1]);
            float2 v1 = make_float2(acc[mt][nt][2], acc[mt][nt][3]);
            if (addb) {
                float2 bb = *(const float2*)&b1[n];
                v0.x += bb.x; v0.y += bb.y;
                v1.x += bb.x; v1.y += bb.y;
            }
            *(float2*)&outp[(size_t)m * HID + n] = v0;
            *(float2*)&outp[(size_t)(m + 8) * HID + n] = v1;
        }
    }
}

// ---------------------------------------------------------------------------
// Kernel 2: pairwise relu + reduce to O=2 — register-prefetched fills.
// Tile 16s x 16t, grid (8, 8, 4) = 256 CTAs, 256 threads.
// 4 h-groups of 64 threads (192 h each, 6 chunks of 32 h); thread tile
// 2s x 2t. Next chunk's global loads (both split-K partials + W2) issued
// into registers right after the fill-sync, consumed at the next STS —
// global latency hidden behind the compute phase. 2-step smem tree.
// ---------------------------------------------------------------------------
#define QLD 36
#define QA_G (16 * QLD)                      // 576 floats per group
#define QB_BASE (4 * QA_G)                   // 2304
#define QW_BASE (QB_BASE + 4 * QA_G)         // 4608
#define QW_G 72

__global__ __launch_bounds__(256) void pair_kernel(
    const float* __restrict__ W2, const float* __restrict__ b2,
    float* __restrict__ out)
{
    __shared__ float sm[QW_BASE + 4 * QW_G];     // 19584 B

    const int tt = blockIdx.x;              // t tile (16)
    const int st = blockIdx.y;              // s tile (16)
    const int batch = blockIdx.z;

    const int tid = threadIdx.x;
    const int g  = tid >> 6;                // 0..3 h-group
    const int lt = tid & 63;
    const int sq = lt >> 3;                 // 0..7
    const int tq = lt & 7;                  // 0..7

    float* const sA = sm + g * QA_G;                 // [16][QLD]
    float* const sB = sm + QB_BASE + g * QA_G;       // [16][QLD]
    float* const sW = sm + QW_BASE + g * QW_G;       // [64]

    const float* __restrict__ hap  = g_ha  + (size_t)(batch * SEQ + st * 16) * HID;
    const float* __restrict__ hap2 = g_ha2 + (size_t)(batch * SEQ + st * 16) * HID;
    const float* __restrict__ hbp  = g_hb  + (size_t)(batch * SEQ + tt * 16) * HID;
    const float* __restrict__ hbp2 = g_hb2 + (size_t)(batch * SEQ + tt * 16) * HID;

    // per-thread fill coordinates (2 f4 per array per chunk)
    int frow[2], fcol[2];
    #pragma unroll
    for (int q = 0; q < 2; q++) {
        int f = q * 64 + lt;
        frow[q] = f >> 3;
        fcol[q] = (f & 7) * 4;
    }

    float4 pa[2], pa2[2], pb[2], pb2[2], pw;

    auto ldg_chunk = [&](int c) {
        const int h0 = g * 192 + c * 32;
        #pragma unroll
        for (int q = 0; q < 2; q++) {
            size_t off = (size_t)frow[q] * HID + h0 + fcol[q];
            pa[q]  = *(const float4*)&hap [off];
            pa2[q] = *(const float4*)&hap2[off];
            pb[q]  = *(const float4*)&hbp [off];
            pb2[q] = *(const float4*)&hbp2[off];
        }
        if (lt < 16) pw = *(const float4*)&W2[h0 * 2 + lt * 4];
    };

    float acc[2][2][2] = {};                // [i(s)][j(t)][o]

    ldg_chunk(0);

    #pragma unroll 1
    for (int c = 0; c < 6; c++) {
        // STS the prefetched chunk (merging split-K partials)
        #pragma unroll
        for (int q = 0; q < 2; q++) {
            float4 u = pa[q], u2 = pa2[q];
            u.x += u2.x; u.y += u2.y; u.z += u2.z; u.w += u2.w;
            *(float4*)&sA[frow[q] * QLD + fcol[q]] = u;
            float4 v = pb[q], v2 = pb2[q];
            v.x += v2.x; v.y += v2.y; v.z += v2.z; v.w += v2.w;
            *(float4*)&sB[frow[q] * QLD + fcol[q]] = v;
        }
        if (lt < 16) *(float4*)&sW[lt * 4] = pw;
        __syncthreads();

        if (c + 1 < 6) ldg_chunk(c + 1);    // overlaps with compute below

        #pragma unroll
        for (int hh = 0; hh < 32; hh += 4) {
            float4 A[2], B[2];
            A[0] = *(const float4*)&sA[sq * QLD + hh];
            A[1] = *(const float4*)&sA[(sq + 8) * QLD + hh];
            B[0] = *(const float4*)&sB[tq * QLD + hh];
            B[1] = *(const float4*)&sB[(tq + 8) * QLD + hh];
            float4 W0 = *(const float4*)&sW[2 * hh];
            float4 W1 = *(const float4*)&sW[2 * hh + 4];

            #pragma unroll
            for (int i = 0; i < 2; i++) {
                #pragma unroll
                for (int j = 0; j < 2; j++) {
                    float r;
                    r = fmaxf(A[i].x + B[j].x, 0.f);
                    acc[i][j][0] += r * W0.x; acc[i][j][1] += r * W0.y;
                    r = fmaxf(A[i].y + B[j].y, 0.f);
                    acc[i][j][0] += r * W0.z; acc[i][j][1] += r * W0.w;
                    r = fmaxf(A[i].z + B[j].z, 0.f);
                    acc[i][j][0] += r * W1.x; acc[i][j][1] += r * W1.y;
                    r = fmaxf(A[i].w + B[j].w, 0.f);
                    acc[i][j][0] += r * W1.z; acc[i][j][1] += r * W1.w;
                }
            }
        }
        __syncthreads();
    }

    // ---- 2-step tree reduction across the 4 h-groups (alias over sm) ----
    float (*red)[64][12] = reinterpret_cast<float (*)[64][12]>(sm);
    float* af = (float*)acc;                // 8 floats
    // 4 -> 2
    if (g >= 2) {
        *(float4*)&red[g - 2][lt][0] = *(const float4*)&af[0];
        *(float4*)&red[g - 2][lt][4] = *(const float4*)&af[4];
    }
    __syncthreads();
    if (g < 2) {
        #pragma unroll
        for (int k = 0; k < 8; k++) af[k] += red[g][lt][k];
    }
    __syncthreads();
    // 2 -> 1
    if (g == 1) {
        *(float4*)&red[0][lt][0] = *(const float4*)&af[0];
        *(float4*)&red[0][lt][4] = *(const float4*)&af[4];
    }
    __syncthreads();
    if (g == 0) {
        const float c0 = b2[0], c1 = b2[1];
        #pragma unroll
        for (int i = 0; i < 2; i++) {
            #pragma unroll
            for (int j = 0; j < 2; j++) {
                int k0i = (i * 2 + j) * 2;
                float v0 = acc[i][j][0] + red[0][lt][k0i]     + c0;
                float v1 = acc[i][j][1] + red[0][lt][k0i + 1] + c1;
                int s = st * 16 + sq + 8 * i;
                int t = tt * 16 + tq + 8 * j;
                *(float2*)&out[(((size_t)batch * SEQ + s) * SEQ + t) * NOUT]
                    = make_float2(v0, v1);
            }
        }
    }
}

// ---------------------------------------------------------------------------
extern "C" void kernel_launch(void* const* d_in, const int* in_sizes, int n_in,
                              void* d_out, int out_size)
{
    const float* a  = (const float*)d_in[0];
    const float* b  = (const float*)d_in[1];
    const float* W1 = (const float*)d_in[2];
    const float* b1 = (const float*)d_in[3];
    const float* W2 = (const float*)d_in[4];
    const float* b2 = (const float*)d_in[5];
    float* out = (float*)d_out;

    cudaFuncSetAttribute(proj_tc, cudaFuncAttributeMaxDynamicSharedMemorySize,
                         PROJ_SMEM_BYTES);

    proj_tc<<<dim3(HID / 64, MROWS / 64, 4), 128, PROJ_SMEM_BYTES>>>(a, b, W1, b1);
    pair_kernel<<<dim3(SEQ / 16, SEQ / 16, BS), 256>>>(W2, b2, out);
}